// round 14
// baseline (speedup 1.0000x reference)
#include <cuda_runtime.h>
#include <cuda_bf16.h>

#define NMAX   50000
#define D      96
#define D4     24
#define TM     128
#define STRW   104    // Wt tile row stride (bf16 elems)
#define NCVT   4      // weight-converter blocks appended to scatter grid

typedef unsigned int  u32;
typedef unsigned short ushort_t;

#define W_ELEMS (D * STRW)    // 9984 (pad cols 96..103 never read by MMA)

// ---------------- scratch (device globals; no allocation allowed) ----------
// INVARIANT: g_pool, g_sum, g_sumsq are all-zero at kernel_launch entry
// (module-load zero for call #1; apply_kernel re-zeroes pool, scatter block 0
//  re-zeroes the BN accumulators, both before their next readers).
__device__ float4   g_pool[NMAX * D4];          // pooled neighbor sums (19.2 MB)
__device__ float    g_sum[D];
__device__ float    g_sumsq[D];
__device__ ushort_t g_W1hi[W_ELEMS], g_W1lo[W_ELEMS];
__device__ ushort_t g_W2hi[W_ELEMS], g_W2lo[W_ELEMS];

// ---------------- K1: edge scatter + BN-accum zero + weight pre-split -------
// Edge blocks: 8 threads/edge, 3 float4 chunks each (chunks j, j+8, j+16).
// Last NCVT blocks: convert W1/W2 to transposed bf16-split layout instead.
__global__ void scatter_kernel(const float4* __restrict__ feat,
                               const int* __restrict__ src,
                               const int* __restrict__ dst, int total,
                               const float* __restrict__ W1,
                               const float* __restrict__ W2) {
    const int nEdgeBlocks = gridDim.x - NCVT;
    if ((int)blockIdx.x >= nEdgeBlocks) {
        // ---- weight converter block ----
        int c = blockIdx.x - nEdgeBlocks;             // 0..3
        #pragma unroll
        for (int ii = 0; ii < (D * D / NCVT) / 256; ii++) {   // 9 iters
            int i  = c * (D * D / NCVT) + ii * 256 + threadIdx.x;
            int k  = i / D;
            int nn = i - k * D;
            int off = nn * STRW + k;
            float wv1 = __ldg(W1 + i);
            float wv2 = __ldg(W2 + i);
            __nv_bfloat16 h1v = __float2bfloat16(wv1);
            __nv_bfloat16 h2v = __float2bfloat16(wv2);
            g_W1hi[off] = __bfloat16_as_ushort(h1v);
            g_W1lo[off] = __bfloat16_as_ushort(
                              __float2bfloat16(wv1 - __bfloat162float(h1v)));
            g_W2hi[off] = __bfloat16_as_ushort(h2v);
            g_W2lo[off] = __bfloat16_as_ushort(
                              __float2bfloat16(wv2 - __bfloat162float(h2v)));
        }
        return;
    }
    if (blockIdx.x == 0 && threadIdx.x < 2 * D) {
        // re-zero BN accumulators for this launch (ordered before mlp_kernel)
        if (threadIdx.x < D) g_sum[threadIdx.x] = 0.f;
        else                 g_sumsq[threadIdx.x - D] = 0.f;
    }
    int i = blockIdx.x * blockDim.x + threadIdx.x;
    if (i >= total) return;
    int e = i >> 3;
    int j = i & 7;
    int s = __ldg(src + e);
    int d = __ldg(dst + e);
    const float4* fp = feat + (long)s * D4 + j;
    float4* pp = g_pool + (long)d * D4 + j;
    float4 v0 = __ldg(fp);
    float4 v1 = __ldg(fp + 8);
    float4 v2 = __ldg(fp + 16);
    asm volatile("red.global.add.v4.f32 [%0], {%1,%2,%3,%4};"
                 :: "l"(pp), "f"(v0.x), "f"(v0.y), "f"(v0.z), "f"(v0.w) : "memory");
    asm volatile("red.global.add.v4.f32 [%0], {%1,%2,%3,%4};"
                 :: "l"(pp + 8), "f"(v1.x), "f"(v1.y), "f"(v1.z), "f"(v1.w) : "memory");
    asm volatile("red.global.add.v4.f32 [%0], {%1,%2,%3,%4};"
                 :: "l"(pp + 16), "f"(v2.x), "f"(v2.y), "f"(v2.z), "f"(v2.w) : "memory");
}

// ---------------- K2: tensor-core MLP + BN stats -----------------------------
// A fragments built directly from global (pool + (1+eps)*feat, bf16-split);
// h1 stays entirely in registers (C-fragment of GEMM1 == A-fragment of GEMM2).
#define MMA_BF16(c, a0, a1, a2, a3, b0, b1) \
    asm volatile("mma.sync.aligned.m16n8k16.row.col.f32.bf16.bf16.f32 " \
                 "{%0,%1,%2,%3}, {%4,%5,%6,%7}, {%8,%9}, {%0,%1,%2,%3};" \
                 : "+f"((c)[0]), "+f"((c)[1]), "+f"((c)[2]), "+f"((c)[3]) \
                 : "r"(a0), "r"(a1), "r"(a2), "r"(a3), "r"(b0), "r"(b1))

__device__ __forceinline__ void split_pack(float v0, float v1, u32& hi, u32& lo) {
    __nv_bfloat162 h = __float22bfloat162_rn(make_float2(v0, v1));
    float2 rf = make_float2(v0 - __bfloat162float(h.x),
                            v1 - __bfloat162float(h.y));
    __nv_bfloat162 l = __float22bfloat162_rn(rf);
    hi = *(u32*)&h;
    lo = *(u32*)&l;
}

#define W_VEC (W_ELEMS * 2 / 16)   // 1248 uint4 per weight array

__global__ __launch_bounds__(256, 2)
void mlp_kernel(const float* __restrict__ featf,
                const float* __restrict__ eps,
                const float* __restrict__ b1, const float* __restrict__ b2,
                float* __restrict__ out, int n) {
    extern __shared__ ushort_t smem[];
    ushort_t* W1hi = smem;
    ushort_t* W1lo = W1hi + W_ELEMS;
    ushort_t* W2hi = W1lo + W_ELEMS;
    ushort_t* W2lo = W2hi + W_ELEMS;
    float* s_sum = (float*)(W2lo + W_ELEMS);
    float* s_sq  = s_sum + D;

    const int tid  = threadIdx.x;
    const int lane = tid & 31;
    const int warp = tid >> 5;           // warp owns rows [warp*16, +16)
    const int tq   = lane & 3;
    const int g    = lane >> 2;
    const int rb   = blockIdx.x * TM;

    if (tid < D) { s_sum[tid] = 0.f; s_sq[tid] = 0.f; }

    // ---- stage pre-split weights: pure uint4 copies ----
    {
        uint4* d1h = (uint4*)W1hi; const uint4* s1h = (const uint4*)g_W1hi;
        uint4* d1l = (uint4*)W1lo; const uint4* s1l = (const uint4*)g_W1lo;
        uint4* d2h = (uint4*)W2hi; const uint4* s2h = (const uint4*)g_W2hi;
        uint4* d2l = (uint4*)W2lo; const uint4* s2l = (const uint4*)g_W2lo;
        for (int i = tid; i < W_VEC; i += 256) {
            d1h[i] = __ldg(s1h + i);
            d1l[i] = __ldg(s1l + i);
            d2h[i] = __ldg(s2h + i);
            d2l[i] = __ldg(s2l + i);
        }
    }
    __syncthreads();

    const float se   = 1.0f + __ldg(eps);
    const int   row0 = rb + warp * 16 + g;      // global rows this lane covers
    const int   row1 = row0 + 8;
    const bool  ok0  = row0 < n;
    const bool  ok1  = row1 < n;
    const float2* pool2 = (const float2*)g_pool;
    const float2* feat2 = (const float2*)featf;
    const float2  z2 = make_float2(0.f, 0.f);

    float c[12][4];
    #pragma unroll
    for (int nt = 0; nt < 12; nt++)
        #pragma unroll
        for (int q = 0; q < 4; q++) c[nt][q] = 0.f;

    // ---- GEMM1: A frags direct from global ----
    #pragma unroll
    for (int kt = 0; kt < 6; kt++) {
        int kc = kt * 16 + tq * 2;          // even column
        long i00 = (long)row0 * 48 + (kc >> 1);
        long i10 = (long)row1 * 48 + (kc >> 1);
        float2 p00 = ok0 ? pool2[i00]     : z2;
        float2 p10 = ok1 ? pool2[i10]     : z2;
        float2 p01 = ok0 ? pool2[i00 + 4] : z2;   // +8 cols = +4 float2
        float2 p11 = ok1 ? pool2[i10 + 4] : z2;
        float2 f00 = ok0 ? __ldg(feat2 + i00)     : z2;
        float2 f10 = ok1 ? __ldg(feat2 + i10)     : z2;
        float2 f01 = ok0 ? __ldg(feat2 + i00 + 4) : z2;
        float2 f11 = ok1 ? __ldg(feat2 + i10 + 4) : z2;
        u32 ah[4], al[4];
        split_pack(fmaf(se, f00.x, p00.x), fmaf(se, f00.y, p00.y), ah[0], al[0]);
        split_pack(fmaf(se, f10.x, p10.x), fmaf(se, f10.y, p10.y), ah[1], al[1]);
        split_pack(fmaf(se, f01.x, p01.x), fmaf(se, f01.y, p01.y), ah[2], al[2]);
        split_pack(fmaf(se, f11.x, p11.x), fmaf(se, f11.y, p11.y), ah[3], al[3]);
        #pragma unroll
        for (int nt = 0; nt < 12; nt++) {
            const ushort_t* pbh = W1hi + (nt * 8 + g) * STRW + kc;
            const ushort_t* pbl = W1lo + (nt * 8 + g) * STRW + kc;
            u32 bh0 = *(const u32*)(pbh);
            u32 bh1 = *(const u32*)(pbh + 8);
            u32 bl0 = *(const u32*)(pbl);
            u32 bl1 = *(const u32*)(pbl + 8);
            MMA_BF16(c[nt], ah[0], ah[1], ah[2], ah[3], bh0, bh1);
            MMA_BF16(c[nt], ah[0], ah[1], ah[2], ah[3], bl0, bl1);
            MMA_BF16(c[nt], al[0], al[1], al[2], al[3], bh0, bh1);
        }
    }

    // ---- h1 = relu(c + b1), packed in registers (== GEMM2 A-fragments) ----
    u32 hh[12][2], hl[12][2];
    #pragma unroll
    for (int nt = 0; nt < 12; nt++) {
        int n0 = nt * 8 + tq * 2;
        float bb0 = __ldg(b1 + n0);
        float bb1 = __ldg(b1 + n0 + 1);
        float v00 = fmaxf(c[nt][0] + bb0, 0.f);
        float v01 = fmaxf(c[nt][1] + bb1, 0.f);
        float v10 = fmaxf(c[nt][2] + bb0, 0.f);
        float v11 = fmaxf(c[nt][3] + bb1, 0.f);
        split_pack(v00, v01, hh[nt][0], hl[nt][0]);
        split_pack(v10, v11, hh[nt][1], hl[nt][1]);
    }

    #pragma unroll
    for (int nt = 0; nt < 12; nt++)
        #pragma unroll
        for (int q = 0; q < 4; q++) c[nt][q] = 0.f;

    // ---- GEMM2: A frags straight from h1 registers ----
    #pragma unroll
    for (int kt = 0; kt < 6; kt++) {
        int kc = kt * 16 + tq * 2;
        u32 ah0 = hh[2 * kt][0],     al0 = hl[2 * kt][0];
        u32 ah1 = hh[2 * kt][1],     al1 = hl[2 * kt][1];
        u32 ah2 = hh[2 * kt + 1][0], al2 = hl[2 * kt + 1][0];
        u32 ah3 = hh[2 * kt + 1][1], al3 = hl[2 * kt + 1][1];
        #pragma unroll
        for (int nt = 0; nt < 12; nt++) {
            const ushort_t* pbh = W2hi + (nt * 8 + g) * STRW + kc;
            const ushort_t* pbl = W2lo + (nt * 8 + g) * STRW + kc;
            u32 bh0 = *(const u32*)(pbh);
            u32 bh1 = *(const u32*)(pbh + 8);
            u32 bl0 = *(const u32*)(pbl);
            u32 bl1 = *(const u32*)(pbl + 8);
            MMA_BF16(c[nt], ah0, ah1, ah2, ah3, bh0, bh1);
            MMA_BF16(c[nt], ah0, ah1, ah2, ah3, bl0, bl1);
            MMA_BF16(c[nt], al0, al1, al2, al3, bh0, bh1);
        }
    }

    // ---- epilogue: +b2, store h2, BN sums ----
    #pragma unroll
    for (int nt = 0; nt < 12; nt++) {
        int n0 = nt * 8 + tq * 2;
        float bb0 = __ldg(b2 + n0);
        float bb1 = __ldg(b2 + n0 + 1);
        float v00 = c[nt][0] + bb0;
        float v01 = c[nt][1] + bb1;
        float v10 = c[nt][2] + bb0;
        float v11 = c[nt][3] + bb1;
        float s0 = 0.f, s1 = 0.f, q0 = 0.f, q1 = 0.f;
        if (ok0) {
            *(float2*)(out + (long)row0 * D + n0) = make_float2(v00, v01);
            s0 += v00; s1 += v01; q0 += v00 * v00; q1 += v01 * v01;
        }
        if (ok1) {
            *(float2*)(out + (long)row1 * D + n0) = make_float2(v10, v11);
            s0 += v10; s1 += v11; q0 += v10 * v10; q1 += v11 * v11;
        }
        #pragma unroll
        for (int m = 4; m < 32; m <<= 1) {
            s0 += __shfl_xor_sync(0xffffffffu, s0, m);
            s1 += __shfl_xor_sync(0xffffffffu, s1, m);
            q0 += __shfl_xor_sync(0xffffffffu, q0, m);
            q1 += __shfl_xor_sync(0xffffffffu, q1, m);
        }
        if (g == 0) {
            atomicAdd(&s_sum[n0],     s0);
            atomicAdd(&s_sum[n0 + 1], s1);
            atomicAdd(&s_sq[n0],      q0);
            atomicAdd(&s_sq[n0 + 1],  q1);
        }
    }
    __syncthreads();
    if (tid < D) {
        atomicAdd(&g_sum[tid],   s_sum[tid]);
        atomicAdd(&g_sumsq[tid], s_sq[tid]);
    }
}

// ---------------- K3: apply BN + ReLU; re-zero pool for next replay ----------
__global__ void apply_kernel(const float* __restrict__ gamma,
                             const float* __restrict__ beta,
                             float invN, float4* __restrict__ out4, int n4) {
    __shared__ __align__(16) float sc[D];
    __shared__ __align__(16) float sh[D];
    int tid = threadIdx.x;
    if (tid < D) {
        float mean = g_sum[tid] * invN;
        float var  = g_sumsq[tid] * invN - mean * mean;
        float rstd = rsqrtf(var + 1e-5f);
        float s    = rstd * gamma[tid];
        sc[tid] = s;
        sh[tid] = beta[tid] - mean * s;
    }
    __syncthreads();

    int i = blockIdx.x * blockDim.x + tid;
    if (i >= n4) return;
    g_pool[i] = make_float4(0.f, 0.f, 0.f, 0.f);   // invariant for next launch
    int c4 = i % D4;
    float4 h  = out4[i];
    float4 s4 = ((const float4*)sc)[c4];
    float4 h4 = ((const float4*)sh)[c4];
    h.x = fmaxf(fmaf(h.x, s4.x, h4.x), 0.f);
    h.y = fmaxf(fmaf(h.y, s4.y, h4.y), 0.f);
    h.z = fmaxf(fmaf(h.z, s4.z, h4.z), 0.f);
    h.w = fmaxf(fmaf(h.w, s4.w, h4.w), 0.f);
    out4[i] = h;
}

// ---------------------------------------------------------------------------
extern "C" void kernel_launch(void* const* d_in, const int* in_sizes, int n_in,
                              void* d_out, int out_size) {
    const float* feature = (const float*)d_in[0];
    const int*   src     = (const int*)d_in[1];
    const int*   dst     = (const int*)d_in[2];
    const float* W1      = (const float*)d_in[3];
    const float* b1      = (const float*)d_in[4];
    const float* W2      = (const float*)d_in[5];
    const float* b2      = (const float*)d_in[6];
    const float* gamma   = (const float*)d_in[7];
    const float* beta    = (const float*)d_in[8];
    const float* eps     = (const float*)d_in[9];
    float* out = (float*)d_out;

    const int n  = in_sizes[0] / D;     // 50000
    const int E  = in_sizes[1];         // 800000
    const int n4 = n * D4;

    int total = E * 8;
    int edgeBlocks = (total + 255) / 256;
    scatter_kernel<<<edgeBlocks + NCVT, 256>>>((const float4*)feature,
                                               src, dst, total, W1, W2);

    const int SMEM = 4 * W_ELEMS * 2 + 2 * D * 4;   // 80640 B
    cudaFuncSetAttribute(mlp_kernel,
                         cudaFuncAttributeMaxDynamicSharedMemorySize, SMEM);
    mlp_kernel<<<(n + TM - 1) / TM, 256, SMEM>>>(feature, eps,
                                                 b1, b2, out, n);

    apply_kernel<<<(n4 + 255) / 256, 256>>>(gamma, beta, 1.0f / (float)n,
                                            (float4*)out, n4);
}

// round 15
// speedup vs baseline: 1.0360x; 1.0360x over previous
#include <cuda_runtime.h>
#include <cuda_bf16.h>

#define NMAX   50000
#define D      96
#define D4     24
#define TM     128
#define STRW   104    // Wt tile row stride (bf16 elems)

typedef unsigned int  u32;
typedef unsigned short ushort_t;

#define W_ELEMS (D * STRW)    // 9984

// ---------------- scratch (device globals; no allocation allowed) ----------
// INVARIANT: g_pool, g_sum, g_sumsq are all-zero at kernel_launch entry
// (module-load zero for call #1; apply_kernel re-zeroes pool, scatter block 0
//  re-zeroes the BN accumulators, both before their next readers).
__device__ float4 g_pool[NMAX * D4];            // pooled neighbor sums (19.2 MB)
__device__ float  g_sum[D];
__device__ float  g_sumsq[D];

// ---------------- K1: edge scatter: pool[dst] += feature[src] ---------------
// 8 threads per edge, 3 float4 chunks per thread (chunks j, j+8, j+16)
__global__ void scatter_kernel(const float4* __restrict__ feat,
                               const int* __restrict__ src,
                               const int* __restrict__ dst, int total) {
    if (blockIdx.x == 0 && threadIdx.x < 2 * D) {
        // re-zero BN accumulators for this launch (ordered before mlp_kernel)
        if (threadIdx.x < D) g_sum[threadIdx.x] = 0.f;
        else                 g_sumsq[threadIdx.x - D] = 0.f;
    }
    int i = blockIdx.x * blockDim.x + threadIdx.x;
    if (i >= total) return;
    int e = i >> 3;
    int j = i & 7;
    int s = __ldg(src + e);
    int d = __ldg(dst + e);
    const float4* fp = feat + (long)s * D4 + j;
    float4* pp = g_pool + (long)d * D4 + j;
    float4 v0 = __ldg(fp);
    float4 v1 = __ldg(fp + 8);
    float4 v2 = __ldg(fp + 16);
    asm volatile("red.global.add.v4.f32 [%0], {%1,%2,%3,%4};"
                 :: "l"(pp), "f"(v0.x), "f"(v0.y), "f"(v0.z), "f"(v0.w) : "memory");
    asm volatile("red.global.add.v4.f32 [%0], {%1,%2,%3,%4};"
                 :: "l"(pp + 8), "f"(v1.x), "f"(v1.y), "f"(v1.z), "f"(v1.w) : "memory");
    asm volatile("red.global.add.v4.f32 [%0], {%1,%2,%3,%4};"
                 :: "l"(pp + 16), "f"(v2.x), "f"(v2.y), "f"(v2.z), "f"(v2.w) : "memory");
}

// ---------------- K2: tensor-core MLP + BN stats -----------------------------
// A fragments built directly from global (pool + (1+eps)*feat, bf16-split);
// h1 stays entirely in registers (C-fragment of GEMM1 == A-fragment of GEMM2).
#define MMA_BF16(c, a0, a1, a2, a3, b0, b1) \
    asm volatile("mma.sync.aligned.m16n8k16.row.col.f32.bf16.bf16.f32 " \
                 "{%0,%1,%2,%3}, {%4,%5,%6,%7}, {%8,%9}, {%0,%1,%2,%3};" \
                 : "+f"((c)[0]), "+f"((c)[1]), "+f"((c)[2]), "+f"((c)[3]) \
                 : "r"(a0), "r"(a1), "r"(a2), "r"(a3), "r"(b0), "r"(b1))

__device__ __forceinline__ void split_pack(float v0, float v1, u32& hi, u32& lo) {
    __nv_bfloat162 h = __float22bfloat162_rn(make_float2(v0, v1));
    float2 rf = make_float2(v0 - __bfloat162float(h.x),
                            v1 - __bfloat162float(h.y));
    __nv_bfloat162 l = __float22bfloat162_rn(rf);
    hi = *(u32*)&h;
    lo = *(u32*)&l;
}

__global__ __launch_bounds__(256, 2)
void mlp_kernel(const float* __restrict__ featf,
                const float* __restrict__ eps,
                const float* __restrict__ W1, const float* __restrict__ b1,
                const float* __restrict__ W2, const float* __restrict__ b2,
                float* __restrict__ out, int n) {
    extern __shared__ ushort_t smem[];
    ushort_t* W1hi = smem;
    ushort_t* W1lo = W1hi + W_ELEMS;
    ushort_t* W2hi = W1lo + W_ELEMS;
    ushort_t* W2lo = W2hi + W_ELEMS;
    float* s_sum = (float*)(W2lo + W_ELEMS);
    float* s_sq  = s_sum + D;

    const int tid  = threadIdx.x;
    const int lane = tid & 31;
    const int warp = tid >> 5;           // warp owns rows [warp*16, +16)
    const int tq   = lane & 3;
    const int g    = lane >> 2;
    const int rb   = blockIdx.x * TM;

    if (tid < D) { s_sum[tid] = 0.f; s_sq[tid] = 0.f; }

    // ---- stage W1 and W2 transposed (Wt[n][k]), bf16 split ----
    for (int i = tid; i < D * D; i += 256) {
        int k  = i / D;
        int nn = i - k * D;
        int off = nn * STRW + k;
        float wv1 = __ldg(W1 + i);
        float wv2 = __ldg(W2 + i);
        __nv_bfloat16 h1v = __float2bfloat16(wv1);
        __nv_bfloat16 h2v = __float2bfloat16(wv2);
        W1hi[off] = __bfloat16_as_ushort(h1v);
        W1lo[off] = __bfloat16_as_ushort(
                        __float2bfloat16(wv1 - __bfloat162float(h1v)));
        W2hi[off] = __bfloat16_as_ushort(h2v);
        W2lo[off] = __bfloat16_as_ushort(
                        __float2bfloat16(wv2 - __bfloat162float(h2v)));
    }
    __syncthreads();

    const float se   = 1.0f + __ldg(eps);
    const int   row0 = rb + warp * 16 + g;      // global rows this lane covers
    const int   row1 = row0 + 8;
    const bool  ok0  = row0 < n;
    const bool  ok1  = row1 < n;
    const float2* pool2 = (const float2*)g_pool;
    const float2* feat2 = (const float2*)featf;
    const float2  z2 = make_float2(0.f, 0.f);

    float c[12][4];
    #pragma unroll
    for (int nt = 0; nt < 12; nt++)
        #pragma unroll
        for (int q = 0; q < 4; q++) c[nt][q] = 0.f;

    // ---- GEMM1: A frags direct from global ----
    #pragma unroll
    for (int kt = 0; kt < 6; kt++) {
        int kc = kt * 16 + tq * 2;          // even column
        long i00 = (long)row0 * 48 + (kc >> 1);
        long i10 = (long)row1 * 48 + (kc >> 1);
        float2 p00 = ok0 ? pool2[i00]     : z2;
        float2 p10 = ok1 ? pool2[i10]     : z2;
        float2 p01 = ok0 ? pool2[i00 + 4] : z2;   // +8 cols = +4 float2
        float2 p11 = ok1 ? pool2[i10 + 4] : z2;
        float2 f00 = ok0 ? __ldg(feat2 + i00)     : z2;
        float2 f10 = ok1 ? __ldg(feat2 + i10)     : z2;
        float2 f01 = ok0 ? __ldg(feat2 + i00 + 4) : z2;
        float2 f11 = ok1 ? __ldg(feat2 + i10 + 4) : z2;
        u32 ah[4], al[4];
        split_pack(fmaf(se, f00.x, p00.x), fmaf(se, f00.y, p00.y), ah[0], al[0]);
        split_pack(fmaf(se, f10.x, p10.x), fmaf(se, f10.y, p10.y), ah[1], al[1]);
        split_pack(fmaf(se, f01.x, p01.x), fmaf(se, f01.y, p01.y), ah[2], al[2]);
        split_pack(fmaf(se, f11.x, p11.x), fmaf(se, f11.y, p11.y), ah[3], al[3]);
        #pragma unroll
        for (int nt = 0; nt < 12; nt++) {
            const ushort_t* pbh = W1hi + (nt * 8 + g) * STRW + kc;
            const ushort_t* pbl = W1lo + (nt * 8 + g) * STRW + kc;
            u32 bh0 = *(const u32*)(pbh);
            u32 bh1 = *(const u32*)(pbh + 8);
            u32 bl0 = *(const u32*)(pbl);
            u32 bl1 = *(const u32*)(pbl + 8);
            MMA_BF16(c[nt], ah[0], ah[1], ah[2], ah[3], bh0, bh1);
            MMA_BF16(c[nt], ah[0], ah[1], ah[2], ah[3], bl0, bl1);
            MMA_BF16(c[nt], al[0], al[1], al[2], al[3], bh0, bh1);
        }
    }

    // ---- h1 = relu(c + b1), packed in registers (== GEMM2 A-fragments) ----
    u32 hh[12][2], hl[12][2];
    #pragma unroll
    for (int nt = 0; nt < 12; nt++) {
        int n0 = nt * 8 + tq * 2;
        float bb0 = __ldg(b1 + n0);
        float bb1 = __ldg(b1 + n0 + 1);
        float v00 = fmaxf(c[nt][0] + bb0, 0.f);
        float v01 = fmaxf(c[nt][1] + bb1, 0.f);
        float v10 = fmaxf(c[nt][2] + bb0, 0.f);
        float v11 = fmaxf(c[nt][3] + bb1, 0.f);
        split_pack(v00, v01, hh[nt][0], hl[nt][0]);
        split_pack(v10, v11, hh[nt][1], hl[nt][1]);
    }

    #pragma unroll
    for (int nt = 0; nt < 12; nt++)
        #pragma unroll
        for (int q = 0; q < 4; q++) c[nt][q] = 0.f;

    // ---- GEMM2: A frags straight from h1 registers ----
    #pragma unroll
    for (int kt = 0; kt < 6; kt++) {
        int kc = kt * 16 + tq * 2;
        u32 ah0 = hh[2 * kt][0],     al0 = hl[2 * kt][0];
        u32 ah1 = hh[2 * kt][1],     al1 = hl[2 * kt][1];
        u32 ah2 = hh[2 * kt + 1][0], al2 = hl[2 * kt + 1][0];
        u32 ah3 = hh[2 * kt + 1][1], al3 = hl[2 * kt + 1][1];
        #pragma unroll
        for (int nt = 0; nt < 12; nt++) {
            const ushort_t* pbh = W2hi + (nt * 8 + g) * STRW + kc;
            const ushort_t* pbl = W2lo + (nt * 8 + g) * STRW + kc;
            u32 bh0 = *(const u32*)(pbh);
            u32 bh1 = *(const u32*)(pbh + 8);
            u32 bl0 = *(const u32*)(pbl);
            u32 bl1 = *(const u32*)(pbl + 8);
            MMA_BF16(c[nt], ah0, ah1, ah2, ah3, bh0, bh1);
            MMA_BF16(c[nt], ah0, ah1, ah2, ah3, bl0, bl1);
            MMA_BF16(c[nt], al0, al1, al2, al3, bh0, bh1);
        }
    }

    // ---- epilogue: +b2, store h2, BN sums ----
    #pragma unroll
    for (int nt = 0; nt < 12; nt++) {
        int n0 = nt * 8 + tq * 2;
        float bb0 = __ldg(b2 + n0);
        float bb1 = __ldg(b2 + n0 + 1);
        float v00 = c[nt][0] + bb0;
        float v01 = c[nt][1] + bb1;
        float v10 = c[nt][2] + bb0;
        float v11 = c[nt][3] + bb1;
        float s0 = 0.f, s1 = 0.f, q0 = 0.f, q1 = 0.f;
        if (ok0) {
            *(float2*)(out + (long)row0 * D + n0) = make_float2(v00, v01);
            s0 += v00; s1 += v01; q0 += v00 * v00; q1 += v01 * v01;
        }
        if (ok1) {
            *(float2*)(out + (long)row1 * D + n0) = make_float2(v10, v11);
            s0 += v10; s1 += v11; q0 += v10 * v10; q1 += v11 * v11;
        }
        #pragma unroll
        for (int m = 4; m < 32; m <<= 1) {
            s0 += __shfl_xor_sync(0xffffffffu, s0, m);
            s1 += __shfl_xor_sync(0xffffffffu, s1, m);
            q0 += __shfl_xor_sync(0xffffffffu, q0, m);
            q1 += __shfl_xor_sync(0xffffffffu, q1, m);
        }
        if (g == 0) {
            atomicAdd(&s_sum[n0],     s0);
            atomicAdd(&s_sum[n0 + 1], s1);
            atomicAdd(&s_sq[n0],      q0);
            atomicAdd(&s_sq[n0 + 1],  q1);
        }
    }
    __syncthreads();
    if (tid < D) {
        atomicAdd(&g_sum[tid],   s_sum[tid]);
        atomicAdd(&g_sumsq[tid], s_sq[tid]);
    }
}

// ---------------- K3: apply BN + ReLU; re-zero pool for next replay ----------
__global__ void apply_kernel(const float* __restrict__ gamma,
                             const float* __restrict__ beta,
                             float invN, float4* __restrict__ out4, int n4) {
    __shared__ __align__(16) float sc[D];
    __shared__ __align__(16) float sh[D];
    int tid = threadIdx.x;
    if (tid < D) {
        float mean = g_sum[tid] * invN;
        float var  = g_sumsq[tid] * invN - mean * mean;
        float rstd = rsqrtf(var + 1e-5f);
        float s    = rstd * gamma[tid];
        sc[tid] = s;
        sh[tid] = beta[tid] - mean * s;
    }
    __syncthreads();

    int i = blockIdx.x * blockDim.x + tid;
    if (i >= n4) return;
    g_pool[i] = make_float4(0.f, 0.f, 0.f, 0.f);   // invariant for next launch
    int c4 = i % D4;
    float4 h  = out4[i];
    float4 s4 = ((const float4*)sc)[c4];
    float4 h4 = ((const float4*)sh)[c4];
    h.x = fmaxf(fmaf(h.x, s4.x, h4.x), 0.f);
    h.y = fmaxf(fmaf(h.y, s4.y, h4.y), 0.f);
    h.z = fmaxf(fmaf(h.z, s4.z, h4.z), 0.f);
    h.w = fmaxf(fmaf(h.w, s4.w, h4.w), 0.f);
    out4[i] = h;
}

// ---------------------------------------------------------------------------
extern "C" void kernel_launch(void* const* d_in, const int* in_sizes, int n_in,
                              void* d_out, int out_size) {
    const float* feature = (const float*)d_in[0];
    const int*   src     = (const int*)d_in[1];
    const int*   dst     = (const int*)d_in[2];
    const float* W1      = (const float*)d_in[3];
    const float* b1      = (const float*)d_in[4];
    const float* W2      = (const float*)d_in[5];
    const float* b2      = (const float*)d_in[6];
    const float* gamma   = (const float*)d_in[7];
    const float* beta    = (const float*)d_in[8];
    const float* eps     = (const float*)d_in[9];
    float* out = (float*)d_out;

    const int n  = in_sizes[0] / D;     // 50000
    const int E  = in_sizes[1];         // 800000
    const int n4 = n * D4;

    int total = E * 8;
    scatter_kernel<<<(total + 255) / 256, 256>>>((const float4*)feature,
                                                 src, dst, total);

    const int SMEM = 4 * W_ELEMS * 2 + 2 * D * 4;   // 80640 B
    cudaFuncSetAttribute(mlp_kernel,
                         cudaFuncAttributeMaxDynamicSharedMemorySize, SMEM);
    mlp_kernel<<<(n + TM - 1) / TM, 256, SMEM>>>(feature, eps,
                                                 W1, b1, W2, b2, out, n);

    apply_kernel<<<(n4 + 255) / 256, 256>>>(gamma, beta, 1.0f / (float)n,
                                            (float4*)out, n4);
}

// round 17
// speedup vs baseline: 1.0392x; 1.0031x over previous
#include <cuda_runtime.h>
#include <cuda_bf16.h>

#define NMAX   50000
#define D      96
#define D4     24
#define TM     128
#define STRW   104    // Wt tile row stride (bf16 elems)

typedef unsigned int  u32;
typedef unsigned short ushort_t;

#define W_ELEMS (D * STRW)    // 9984

// ---------------- scratch (device globals; no allocation allowed) ----------
// INVARIANT: g_pool, g_sum, g_sumsq are all-zero at kernel_launch entry
// (module-load zero for call #1; apply_kernel re-zeroes pool, scatter block 0
//  re-zeroes the BN accumulators, both before their next readers).
__device__ float4 g_pool[NMAX * D4];            // pooled neighbor sums (19.2 MB)
__device__ float  g_sum[D];
__device__ float  g_sumsq[D];

// ---------------- K1: edge scatter: pool[dst] += feature[src] ---------------
// 8 threads per edge, 3 float4 chunks per thread (chunks j, j+8, j+16).
// launch_dependents at entry: fires once ALL blocks have started (i.e. at the
// start of the last wave), letting mlp blocks dispatch + stage weights under
// scatter's tail; mlp's griddepcontrol.wait still orders pool reads after all
// REDs complete.
__global__ void scatter_kernel(const float4* __restrict__ feat,
                               const int* __restrict__ src,
                               const int* __restrict__ dst, int total) {
    if (threadIdx.x == 0)
        asm volatile("griddepcontrol.launch_dependents;");
    if (blockIdx.x == 0 && threadIdx.x < 2 * D) {
        // re-zero BN accumulators for this launch (ordered before mlp's
        // epilogue atomics, which run after griddepcontrol.wait)
        if (threadIdx.x < D) g_sum[threadIdx.x] = 0.f;
        else                 g_sumsq[threadIdx.x - D] = 0.f;
    }
    int i = blockIdx.x * blockDim.x + threadIdx.x;
    if (i >= total) return;
    int e = i >> 3;
    int j = i & 7;
    int s = __ldg(src + e);
    int d = __ldg(dst + e);
    const float4* fp = feat + (long)s * D4 + j;
    float4* pp = g_pool + (long)d * D4 + j;
    float4 v0 = __ldg(fp);
    float4 v1 = __ldg(fp + 8);
    float4 v2 = __ldg(fp + 16);
    asm volatile("red.global.add.v4.f32 [%0], {%1,%2,%3,%4};"
                 :: "l"(pp), "f"(v0.x), "f"(v0.y), "f"(v0.z), "f"(v0.w) : "memory");
    asm volatile("red.global.add.v4.f32 [%0], {%1,%2,%3,%4};"
                 :: "l"(pp + 8), "f"(v1.x), "f"(v1.y), "f"(v1.z), "f"(v1.w) : "memory");
    asm volatile("red.global.add.v4.f32 [%0], {%1,%2,%3,%4};"
                 :: "l"(pp + 16), "f"(v2.x), "f"(v2.y), "f"(v2.z), "f"(v2.w) : "memory");
}

// ---------------- K2: tensor-core MLP + BN stats -----------------------------
// A fragments built directly from global (pool + (1+eps)*feat, bf16-split);
// h1 stays entirely in registers (C-fragment of GEMM1 == A-fragment of GEMM2).
#define MMA_BF16(c, a0, a1, a2, a3, b0, b1) \
    asm volatile("mma.sync.aligned.m16n8k16.row.col.f32.bf16.bf16.f32 " \
                 "{%0,%1,%2,%3}, {%4,%5,%6,%7}, {%8,%9}, {%0,%1,%2,%3};" \
                 : "+f"((c)[0]), "+f"((c)[1]), "+f"((c)[2]), "+f"((c)[3]) \
                 : "r"(a0), "r"(a1), "r"(a2), "r"(a3), "r"(b0), "r"(b1))

__device__ __forceinline__ void split_pack(float v0, float v1, u32& hi, u32& lo) {
    __nv_bfloat162 h = __float22bfloat162_rn(make_float2(v0, v1));
    float2 rf = make_float2(v0 - __bfloat162float(h.x),
                            v1 - __bfloat162float(h.y));
    __nv_bfloat162 l = __float22bfloat162_rn(rf);
    hi = *(u32*)&h;
    lo = *(u32*)&l;
}

__global__ __launch_bounds__(256, 2)
void mlp_kernel(const float* __restrict__ featf,
                const float* __restrict__ eps,
                const float* __restrict__ W1, const float* __restrict__ b1,
                const float* __restrict__ W2, const float* __restrict__ b2,
                float* __restrict__ out, int n) {
    extern __shared__ ushort_t smem[];
    ushort_t* W1hi = smem;
    ushort_t* W1lo = W1hi + W_ELEMS;
    ushort_t* W2hi = W1lo + W_ELEMS;
    ushort_t* W2lo = W2hi + W_ELEMS;
    float* s_sum = (float*)(W2lo + W_ELEMS);
    float* s_sq  = s_sum + D;

    const int tid  = threadIdx.x;
    const int lane = tid & 31;
    const int warp = tid >> 5;           // warp owns rows [warp*16, +16)
    const int tq   = lane & 3;
    const int g    = lane >> 2;
    const int rb   = blockIdx.x * TM;

    if (tid < D) { s_sum[tid] = 0.f; s_sq[tid] = 0.f; }

    // ---- stage W1 and W2 transposed (Wt[n][k]), bf16 split ----
    // (pool-independent: overlaps the scatter tail under PDL)
    for (int i = tid; i < D * D; i += 256) {
        int k  = i / D;
        int nn = i - k * D;
        int off = nn * STRW + k;
        float wv1 = __ldg(W1 + i);
        float wv2 = __ldg(W2 + i);
        __nv_bfloat16 h1v = __float2bfloat16(wv1);
        __nv_bfloat16 h2v = __float2bfloat16(wv2);
        W1hi[off] = __bfloat16_as_ushort(h1v);
        W1lo[off] = __bfloat16_as_ushort(
                        __float2bfloat16(wv1 - __bfloat162float(h1v)));
        W2hi[off] = __bfloat16_as_ushort(h2v);
        W2lo[off] = __bfloat16_as_ushort(
                        __float2bfloat16(wv2 - __bfloat162float(h2v)));
    }
    __syncthreads();

    // wait for ALL scatter blocks' REDs to complete + become visible
    asm volatile("griddepcontrol.wait;");

    const float se   = 1.0f + __ldg(eps);
    const int   row0 = rb + warp * 16 + g;      // global rows this lane covers
    const int   row1 = row0 + 8;
    const bool  ok0  = row0 < n;
    const bool  ok1  = row1 < n;
    const float2* pool2 = (const float2*)g_pool;
    const float2* feat2 = (const float2*)featf;
    const float2  z2 = make_float2(0.f, 0.f);

    float c[12][4];
    #pragma unroll
    for (int nt = 0; nt < 12; nt++)
        #pragma unroll
        for (int q = 0; q < 4; q++) c[nt][q] = 0.f;

    // ---- GEMM1: A frags direct from global ----
    #pragma unroll
    for (int kt = 0; kt < 6; kt++) {
        int kc = kt * 16 + tq * 2;          // even column
        long i00 = (long)row0 * 48 + (kc >> 1);
        long i10 = (long)row1 * 48 + (kc >> 1);
        float2 p00 = ok0 ? pool2[i00]     : z2;
        float2 p10 = ok1 ? pool2[i10]     : z2;
        float2 p01 = ok0 ? pool2[i00 + 4] : z2;   // +8 cols = +4 float2
        float2 p11 = ok1 ? pool2[i10 + 4] : z2;
        float2 f00 = ok0 ? __ldg(feat2 + i00)     : z2;
        float2 f10 = ok1 ? __ldg(feat2 + i10)     : z2;
        float2 f01 = ok0 ? __ldg(feat2 + i00 + 4) : z2;
        float2 f11 = ok1 ? __ldg(feat2 + i10 + 4) : z2;
        u32 ah[4], al[4];
        split_pack(fmaf(se, f00.x, p00.x), fmaf(se, f00.y, p00.y), ah[0], al[0]);
        split_pack(fmaf(se, f10.x, p10.x), fmaf(se, f10.y, p10.y), ah[1], al[1]);
        split_pack(fmaf(se, f01.x, p01.x), fmaf(se, f01.y, p01.y), ah[2], al[2]);
        split_pack(fmaf(se, f11.x, p11.x), fmaf(se, f11.y, p11.y), ah[3], al[3]);
        #pragma unroll
        for (int nt = 0; nt < 12; nt++) {
            const ushort_t* pbh = W1hi + (nt * 8 + g) * STRW + kc;
            const ushort_t* pbl = W1lo + (nt * 8 + g) * STRW + kc;
            u32 bh0 = *(const u32*)(pbh);
            u32 bh1 = *(const u32*)(pbh + 8);
            u32 bl0 = *(const u32*)(pbl);
            u32 bl1 = *(const u32*)(pbl + 8);
            MMA_BF16(c[nt], ah[0], ah[1], ah[2], ah[3], bh0, bh1);
            MMA_BF16(c[nt], ah[0], ah[1], ah[2], ah[3], bl0, bl1);
            MMA_BF16(c[nt], al[0], al[1], al[2], al[3], bh0, bh1);
        }
    }

    // ---- h1 = relu(c + b1), packed in registers (== GEMM2 A-fragments) ----
    u32 hh[12][2], hl[12][2];
    #pragma unroll
    for (int nt = 0; nt < 12; nt++) {
        int n0 = nt * 8 + tq * 2;
        float bb0 = __ldg(b1 + n0);
        float bb1 = __ldg(b1 + n0 + 1);
        float v00 = fmaxf(c[nt][0] + bb0, 0.f);
        float v01 = fmaxf(c[nt][1] + bb1, 0.f);
        float v10 = fmaxf(c[nt][2] + bb0, 0.f);
        float v11 = fmaxf(c[nt][3] + bb1, 0.f);
        split_pack(v00, v01, hh[nt][0], hl[nt][0]);
        split_pack(v10, v11, hh[nt][1], hl[nt][1]);
    }

    #pragma unroll
    for (int nt = 0; nt < 12; nt++)
        #pragma unroll
        for (int q = 0; q < 4; q++) c[nt][q] = 0.f;

    // ---- GEMM2: A frags straight from h1 registers ----
    #pragma unroll
    for (int kt = 0; kt < 6; kt++) {
        int kc = kt * 16 + tq * 2;
        u32 ah0 = hh[2 * kt][0],     al0 = hl[2 * kt][0];
        u32 ah1 = hh[2 * kt][1],     al1 = hl[2 * kt][1];
        u32 ah2 = hh[2 * kt + 1][0], al2 = hl[2 * kt + 1][0];
        u32 ah3 = hh[2 * kt + 1][1], al3 = hl[2 * kt + 1][1];
        #pragma unroll
        for (int nt = 0; nt < 12; nt++) {
            const ushort_t* pbh = W2hi + (nt * 8 + g) * STRW + kc;
            const ushort_t* pbl = W2lo + (nt * 8 + g) * STRW + kc;
            u32 bh0 = *(const u32*)(pbh);
            u32 bh1 = *(const u32*)(pbh + 8);
            u32 bl0 = *(const u32*)(pbl);
            u32 bl1 = *(const u32*)(pbl + 8);
            MMA_BF16(c[nt], ah0, ah1, ah2, ah3, bh0, bh1);
            MMA_BF16(c[nt], ah0, ah1, ah2, ah3, bl0, bl1);
            MMA_BF16(c[nt], al0, al1, al2, al3, bh0, bh1);
        }
    }

    // ---- epilogue: +b2, store h2, BN sums ----
    #pragma unroll
    for (int nt = 0; nt < 12; nt++) {
        int n0 = nt * 8 + tq * 2;
        float bb0 = __ldg(b2 + n0);
        float bb1 = __ldg(b2 + n0 + 1);
        float v00 = c[nt][0] + bb0;
        float v01 = c[nt][1] + bb1;
        float v10 = c[nt][2] + bb0;
        float v11 = c[nt][3] + bb1;
        float s0 = 0.f, s1 = 0.f, q0 = 0.f, q1 = 0.f;
        if (ok0) {
            *(float2*)(out + (long)row0 * D + n0) = make_float2(v00, v01);
            s0 += v00; s1 += v01; q0 += v00 * v00; q1 += v01 * v01;
        }
        if (ok1) {
            *(float2*)(out + (long)row1 * D + n0) = make_float2(v10, v11);
            s0 += v10; s1 += v11; q0 += v10 * v10; q1 += v11 * v11;
        }
        #pragma unroll
        for (int m = 4; m < 32; m <<= 1) {
            s0 += __shfl_xor_sync(0xffffffffu, s0, m);
            s1 += __shfl_xor_sync(0xffffffffu, s1, m);
            q0 += __shfl_xor_sync(0xffffffffu, q0, m);
            q1 += __shfl_xor_sync(0xffffffffu, q1, m);
        }
        if (g == 0) {
            atomicAdd(&s_sum[n0],     s0);
            atomicAdd(&s_sum[n0 + 1], s1);
            atomicAdd(&s_sq[n0],      q0);
            atomicAdd(&s_sq[n0 + 1],  q1);
        }
    }
    __syncthreads();
    if (tid < D) {
        atomicAdd(&g_sum[tid],   s_sum[tid]);
        atomicAdd(&g_sumsq[tid], s_sq[tid]);
    }
}

// ---------------- K3: apply BN + ReLU; re-zero pool for next replay ----------
__global__ void apply_kernel(const float* __restrict__ gamma,
                             const float* __restrict__ beta,
                             float invN, float4* __restrict__ out4, int n4) {
    __shared__ __align__(16) float sc[D];
    __shared__ __align__(16) float sh[D];
    int tid = threadIdx.x;
    if (tid < D) {
        float mean = g_sum[tid] * invN;
        float var  = g_sumsq[tid] * invN - mean * mean;
        float rstd = rsqrtf(var + 1e-5f);
        float s    = rstd * gamma[tid];
        sc[tid] = s;
        sh[tid] = beta[tid] - mean * s;
    }
    __syncthreads();

    int i = blockIdx.x * blockDim.x + tid;
    if (i >= n4) return;
    g_pool[i] = make_float4(0.f, 0.f, 0.f, 0.f);   // invariant for next launch
    int c4 = i % D4;
    float4 h  = out4[i];
    float4 s4 = ((const float4*)sc)[c4];
    float4 h4 = ((const float4*)sh)[c4];
    h.x = fmaxf(fmaf(h.x, s4.x, h4.x), 0.f);
    h.y = fmaxf(fmaf(h.y, s4.y, h4.y), 0.f);
    h.z = fmaxf(fmaf(h.z, s4.z, h4.z), 0.f);
    h.w = fmaxf(fmaf(h.w, s4.w, h4.w), 0.f);
    out4[i] = h;
}

// ---------------------------------------------------------------------------
extern "C" void kernel_launch(void* const* d_in, const int* in_sizes, int n_in,
                              void* d_out, int out_size) {
    const float* feature = (const float*)d_in[0];
    const int*   src     = (const int*)d_in[1];
    const int*   dst     = (const int*)d_in[2];
    const float* W1      = (const float*)d_in[3];
    const float* b1      = (const float*)d_in[4];
    const float* W2      = (const float*)d_in[5];
    const float* b2      = (const float*)d_in[6];
    const float* gamma   = (const float*)d_in[7];
    const float* beta    = (const float*)d_in[8];
    const float* eps     = (const float*)d_in[9];
    float* out = (float*)d_out;

    const int n  = in_sizes[0] / D;     // 50000
    const int E  = in_sizes[1];         // 800000
    const int n4 = n * D4;

    int total = E * 8;
    scatter_kernel<<<(total + 255) / 256, 256>>>((const float4*)feature,
                                                 src, dst, total);

    const int SMEM = 4 * W_ELEMS * 2 + 2 * D * 4;   // 80640 B
    cudaFuncSetAttribute(mlp_kernel,
                         cudaFuncAttributeMaxDynamicSharedMemorySize, SMEM);

    // PDL launch: mlp may dispatch + run its weight prologue while scatter's
    // last wave drains; griddepcontrol.wait gates the pool reads.
    {
        cudaLaunchConfig_t cfg = {};
        cfg.gridDim  = dim3((n + TM - 1) / TM, 1, 1);
        cfg.blockDim = dim3(256, 1, 1);
        cfg.dynamicSmemBytes = SMEM;
        cfg.stream = 0;
        cudaLaunchAttribute attr[1];
        attr[0].id = cudaLaunchAttributeProgrammaticStreamSerialization;
        attr[0].val.programmaticStreamSerializationAllowed = 1;
        cfg.attrs = attr;
        cfg.numAttrs = 1;
        cudaLaunchKernelEx(&cfg, mlp_kernel, feature, eps,
                           W1, b1, W2, b2, out, n);
    }

    apply_kernel<<<(n4 + 255) / 256, 256>>>(gamma, beta, 1.0f / (float)n,
                                            (float4*)out, n4);
}